// round 16
// baseline (speedup 1.0000x reference)
#include <cuda_runtime.h>
#include <cuda_bf16.h>
#include <stdint.h>

// Problem constants
#define PD 64      // splits
#define KD 64      // samples per side
#define ND 128     // points per split
#define DD 2048    // feature dim
#define NCH 4      // D quarters -> 256 CTAs, 2 per SM
#define KC (DD / NCH)     // 512 K per CTA
#define NCHK (KC / 64)    // 8 chunks of 64 K
#define MSUB 12    // mmd CTAs per split: 4 XX + 4 YY + 4 XY

// Scratch (device globals; zero-initialized; counters self-reset)
__device__ float g_part[NCH][PD][ND][ND];  // partial grams (YX quadrant unwritten)
__device__ float g_diag[NCH][PD][ND];      // partial gram diagonals
__device__ float g_bw[NCH][PD][2];         // per-quarter (strict-upper sum, trace)
__device__ float g_sums2[PD][MSUB];        // per-CTA kernel sums
__device__ float g_l2m[MSUB];              // per-CTA max l2, split PD-1
__device__ unsigned int g_ctr;             // finalize counter (self-reset)

__device__ __forceinline__ uint32_t smem_u32(const void* p) {
    uint32_t a;
    asm("{ .reg .u64 t; cvta.to.shared.u64 t, %1; cvt.u32.u64 %0, t; }"
        : "=r"(a) : "l"(p));
    return a;
}

__device__ __forceinline__ void ldsm_x4(uint32_t& r0, uint32_t& r1, uint32_t& r2,
                                        uint32_t& r3, uint32_t addr) {
    asm volatile("ldmatrix.sync.aligned.m8n8.x4.shared.b16 {%0,%1,%2,%3}, [%4];"
                 : "=r"(r0), "=r"(r1), "=r"(r2), "=r"(r3) : "r"(addr));
}

__device__ __forceinline__ void mma_bf16(float* c, const uint32_t* a, const uint32_t* b) {
    asm volatile(
        "mma.sync.aligned.m16n8k16.row.col.f32.bf16.bf16.f32 "
        "{%0,%1,%2,%3}, {%4,%5,%6,%7}, {%8,%9}, {%0,%1,%2,%3};"
        : "+f"(c[0]), "+f"(c[1]), "+f"(c[2]), "+f"(c[3])
        : "r"(a[0]), "r"(a[1]), "r"(a[2]), "r"(a[3]), "r"(b[0]), "r"(b[1]));
}

// ---------------------------------------------------------------------------
// Kernel 1: partial Gram via HMMA (R10 main loop). Symmetry: warps 2,3 own
// the YX tiles (wm=64/96, wn=0) which are transposes of XY -> they skip
// LDSM/MMA/writeout entirely (25% off the smem pipe). Bandwidth aggregates
// become (strict-upper sum, trace): sum(G) = 2*upper + trace.
// ---------------------------------------------------------------------------
__global__ void __launch_bounds__(256, 2) gram_kernel(const float* __restrict__ src,
                                                      const float* __restrict__ tgt) {
    const int nc = blockIdx.x;
    const int p  = blockIdx.y;
    const int t  = threadIdx.x;
    const int lane = t & 31;
    const int w    = t >> 5;
    const bool mma_active = (w != 2) && (w != 3);

    __shared__ __align__(16) __nv_bfloat16 tile[2][ND][72];
    __shared__ float red1[8], red2[8];

    // ---- loader mapping (all 256 threads) ----
    const int f4 = t & 15;
    const int rb = t >> 4;
    const float* rowp[8];
#pragma unroll
    for (int s = 0; s < 8; s++) {
        int r = rb + 16 * s;
        const float* base = (r < KD) ? (src + (size_t)(p * KD + r) * DD)
                                     : (tgt + (size_t)(p * KD + (r - KD)) * DD);
        rowp[s] = base + nc * KC + f4 * 4;
    }
    char* tbase[2] = { (char*)&tile[0][0][0], (char*)&tile[1][0][0] };
    uint32_t sts[8];
#pragma unroll
    for (int s = 0; s < 8; s++)
        sts[s] = (uint32_t)((rb + 16 * s) * 144 + f4 * 8);

    // ---- mma mapping: warp tile at (wm, wn) ----
    const int wm = (w & 3) << 5;
    const int wn = (w >> 2) << 6;
    uint32_t tb[2] = { smem_u32(tbase[0]), smem_u32(tbase[1]) };
    uint32_t aaddr[2][2], baddr[2][4];
#pragma unroll
    for (int b = 0; b < 2; b++) {
#pragma unroll
        for (int mi = 0; mi < 2; mi++)
            aaddr[b][mi] = tb[b] + (uint32_t)((wm + mi * 16 + (lane & 15)) * 144
                                              + (lane >> 4) * 16);
#pragma unroll
        for (int nj = 0; nj < 4; nj++)
            baddr[b][nj] = tb[b] + (uint32_t)((wn + nj * 16 + ((lane >> 4) << 3)
                                               + (lane & 7)) * 144
                                              + ((lane >> 3) & 1) * 16);
    }

    float acc[2][8][4];
#pragma unroll
    for (int mi = 0; mi < 2; mi++)
#pragma unroll
        for (int nj = 0; nj < 8; nj++)
#pragma unroll
            for (int r = 0; r < 4; r++) acc[mi][nj][r] = 0.f;

    float4 v[8];
#pragma unroll
    for (int s = 0; s < 8; s++) v[s] = *(const float4*)(rowp[s]);
#pragma unroll
    for (int s = 0; s < 8; s++) {
        __nv_bfloat162 lo = __floats2bfloat162_rn(v[s].x, v[s].y);
        __nv_bfloat162 hi = __floats2bfloat162_rn(v[s].z, v[s].w);
        uint2 u = { *(uint32_t*)&lo, *(uint32_t*)&hi };
        *(uint2*)(tbase[0] + sts[s]) = u;
    }
    __syncthreads();

    uint32_t afr[2][2][4], bfr[2][8][2];

    for (int ch = 0; ch < NCHK; ch++) {
        const int b = ch & 1;
        if (ch + 1 < NCHK) {
#pragma unroll
            for (int s = 0; s < 8; s++)
                v[s] = *(const float4*)(rowp[s] + (ch + 1) * 64);
        }

        if (mma_active) {
            ldsm_x4(afr[0][0][0], afr[0][0][1], afr[0][0][2], afr[0][0][3], aaddr[b][0]);
            ldsm_x4(afr[0][1][0], afr[0][1][1], afr[0][1][2], afr[0][1][3], aaddr[b][1]);
#pragma unroll
            for (int nj = 0; nj < 4; nj++)
                ldsm_x4(bfr[0][2 * nj][0], bfr[0][2 * nj][1],
                        bfr[0][2 * nj + 1][0], bfr[0][2 * nj + 1][1], baddr[b][nj]);

#pragma unroll
            for (int k16 = 0; k16 < 4; k16++) {
                const int cur = k16 & 1;
                const int nxt = cur ^ 1;
                if (k16 < 3) {
                    ldsm_x4(afr[nxt][0][0], afr[nxt][0][1], afr[nxt][0][2],
                            afr[nxt][0][3], aaddr[b][0] + (k16 + 1) * 32);
                    ldsm_x4(afr[nxt][1][0], afr[nxt][1][1], afr[nxt][1][2],
                            afr[nxt][1][3], aaddr[b][1] + (k16 + 1) * 32);
#pragma unroll
                    for (int nj = 0; nj < 4; nj++)
                        ldsm_x4(bfr[nxt][2 * nj][0], bfr[nxt][2 * nj][1],
                                bfr[nxt][2 * nj + 1][0], bfr[nxt][2 * nj + 1][1],
                                baddr[b][nj] + (k16 + 1) * 32);
                }
#pragma unroll
                for (int mi = 0; mi < 2; mi++)
#pragma unroll
                    for (int nj = 0; nj < 8; nj++)
                        mma_bf16(acc[mi][nj], afr[cur][mi], bfr[cur][nj]);
            }
        }

        if (ch + 1 < NCHK) {
            char* dst = tbase[(ch + 1) & 1];
#pragma unroll
            for (int s = 0; s < 8; s++) {
                __nv_bfloat162 lo = __floats2bfloat162_rn(v[s].x, v[s].y);
                __nv_bfloat162 hi = __floats2bfloat162_rn(v[s].z, v[s].w);
                uint2 u = { *(uint32_t*)&lo, *(uint32_t*)&hi };
                *(uint2*)(dst + sts[s]) = u;
            }
            __syncthreads();
        }
    }

    // ---- writeout (retained tiles only) + (strict-upper sum, trace) + diag ----
    float s1 = 0.f, s2 = 0.f;
    if (mma_active) {
        float* outp = &g_part[nc][p][0][0];
        float* diagp = &g_diag[nc][p][0];
        const int rr = lane >> 2;
        const int cc = (lane & 3) * 2;
#pragma unroll
        for (int mi = 0; mi < 2; mi++)
#pragma unroll
            for (int nj = 0; nj < 8; nj++) {
                int row = wm + mi * 16 + rr;
                int col = wn + nj * 8 + cc;
                *(float2*)&outp[row * ND + col] =
                    make_float2(acc[mi][nj][0], acc[mi][nj][1]);
                *(float2*)&outp[(row + 8) * ND + col] =
                    make_float2(acc[mi][nj][2], acc[mi][nj][3]);
                // strict-upper sum (col > row)
                if (col > row)         s1 += acc[mi][nj][0];
                if (col + 1 > row)     s1 += acc[mi][nj][1];
                if (col > row + 8)     s1 += acc[mi][nj][2];
                if (col + 1 > row + 8) s1 += acc[mi][nj][3];
                // trace + diag writeout
                if (row == col)         { s2 += acc[mi][nj][0]; diagp[row]     = acc[mi][nj][0]; }
                if (row == col + 1)     { s2 += acc[mi][nj][1]; diagp[row]     = acc[mi][nj][1]; }
                if (row + 8 == col)     { s2 += acc[mi][nj][2]; diagp[row + 8] = acc[mi][nj][2]; }
                if (row + 8 == col + 1) { s2 += acc[mi][nj][3]; diagp[row + 8] = acc[mi][nj][3]; }
            }
    }
#pragma unroll
    for (int m = 16; m > 0; m >>= 1) {
        s1 += __shfl_xor_sync(0xFFFFFFFFu, s1, m);
        s2 += __shfl_xor_sync(0xFFFFFFFFu, s2, m);
    }
    if (lane == 0) { red1[w] = s1; red2[w] = s2; }
    __syncthreads();
    if (t == 0) {
        float a = 0.f, b2 = 0.f;
#pragma unroll
        for (int k = 0; k < 8; k++) { a += red1[k]; b2 += red2[k]; }
        g_bw[nc][p][0] = a;    // strict-upper sum of partial gram
        g_bw[nc][p][1] = b2;   // trace of partial gram
    }
}

// ---------------------------------------------------------------------------
// Kernel 2 (symmetric): 768 CTAs x 256 thr. Per split: 4 XX-upper strips,
// 4 YY-upper strips, 4 XY strips (16 cols each). Diag l2 = 0 -> kernel = 5.0
// per element, added analytically at finalize. xy == yx by symmetry.
// blockIdx.x = sub (0..11: 0-3 XX, 4-7 YY, 8-11 XY), blockIdx.y = split.
// ---------------------------------------------------------------------------
__global__ void __launch_bounds__(256) mmd_kernel(float* __restrict__ out) {
    const int sub = blockIdx.x;
    const int p   = blockIdx.y;
    const int region = sub >> 2;      // 0=XX, 1=YY, 2=XY
    const int jb = (sub & 3) * 16;    // col block within region
    const int t = threadIdx.x;
    const int lane = t & 31;
    const int w = t >> 5;

    const int rr = t >> 2;                       // row within region (0..63)
    const int cg = (t & 3) * 4;                  // col offset within strip
    const int row = (region == 1) ? 64 + rr : rr;
    const int col0 = ((region == 0) ? 0 : 64) + jb + cg;

    __shared__ float praw[4][ND];
    __shared__ float diag[ND];
    __shared__ float sred[8], sred2[8];
    __shared__ unsigned int s_last;

    // cooperative diag load: 128 float4 loads cover g_diag[0..3][p][0..127]
    if (t < 128) {
        int c = t >> 5, i4 = (t & 31) * 4;
        float4 dv = *(const float4*)&g_diag[c][p][i4];
        *(float4*)&praw[c][i4] = dv;
    }
    __syncthreads();
    if (t < 128)
        diag[t] = (praw[0][t] + praw[1][t]) + (praw[2][t] + praw[3][t]);

    // bandwidth: sum(G) = 2*upper + trace; sum(l2) = 2*n*trace - 2*sum(G)
    float gu = 0.f, tr = 0.f;
#pragma unroll
    for (int c = 0; c < NCH; c++) { gu += g_bw[c][p][0]; tr += g_bw[c][p][1]; }
    const float sumG = 2.f * gu + tr;
    const float sumL2 = 2.f * (float)ND * tr - 2.f * sumG;
    const float bwv = sumL2 / (float)(ND * ND - ND) * 0.25f;
    const float inv4 = 1.f / (bwv * 16.f + 1e-9f);
    __syncthreads();

    // active: strict-upper exists in this thread's 4-col group (XX/YY);
    // XY always active. Upper condition uses region-local indices.
    const int jloc0 = jb + cg;                   // region-local first col
    const bool active = (region == 2) || (rr < jloc0 + 3);

    float qs = 0.f, lmax = 0.f;
    if (active) {
        float4 A = *(const float4*)&g_part[0][p][row][col0];
        float4 B = *(const float4*)&g_part[1][p][row][col0];
        float4 C = *(const float4*)&g_part[2][p][row][col0];
        float4 D = *(const float4*)&g_part[3][p][row][col0];
        float g[4] = { (A.x + B.x) + (C.x + D.x),
                       (A.y + B.y) + (C.y + D.y),
                       (A.z + B.z) + (C.z + D.z),
                       (A.w + B.w) + (C.w + D.w) };
        const float di = diag[row];
#pragma unroll
        for (int jj = 0; jj < 4; jj++) {
            bool use = (region == 2) || (jloc0 + jj > rr);
            if (use) {
                float l2 = di + diag[col0 + jj] - 2.f * g[jj];
                lmax = fmaxf(lmax, l2);
                float z = __expf(-l2 * inv4);
                float z2 = z * z;
                float z4 = z2 * z2;
                float z8 = z4 * z4;
                float z16 = z8 * z8;
                qs += z + z2 + z4 + z8 + z16;
            }
        }
    }

#pragma unroll
    for (int m = 16; m > 0; m >>= 1) {
        qs += __shfl_xor_sync(0xFFFFFFFFu, qs, m);
        lmax = fmaxf(lmax, __shfl_xor_sync(0xFFFFFFFFu, lmax, m));
    }
    if (lane == 0) { sred[w] = qs; sred2[w] = lmax; }
    __syncthreads();

    if (t == 0) {
        float s = 0.f, m = 0.f;
#pragma unroll
        for (int k = 0; k < 8; k++) { s += sred[k]; m = fmaxf(m, sred2[k]); }
        g_sums2[p][sub] = s;
        if (p == PD - 1) g_l2m[sub] = m;
        __threadfence();
        unsigned int done = atomicAdd(&g_ctr, 1u);
        s_last = (done == (unsigned)(MSUB * PD - 1)) ? 1u : 0u;
        if (s_last) g_ctr = 0;   // reset for graph replay
    }
    __syncthreads();

    // ---- warp-parallel finalize (fixed order, deterministic) ----
    if (s_last != 0 && w == 0) {
        __threadfence();   // acquire: prior CTAs released via fence+atomic
        float X = 0.f, Y = 0.f, XY = 0.f;
#pragma unroll
        for (int pp = lane; pp < PD; pp += 32) {
            const float* s = &g_sums2[pp][0];
            float4 a0 = *(const float4*)&s[0];    // XX upper strips
            float4 a1 = *(const float4*)&s[4];    // YY upper strips
            float4 a2 = *(const float4*)&s[8];    // XY strips
            X  += (a0.x + a0.y) + (a0.z + a0.w);
            Y  += (a1.x + a1.y) + (a1.z + a1.w);
            XY += (a2.x + a2.y) + (a2.z + a2.w);
        }
#pragma unroll
        for (int m = 16; m > 0; m >>= 1) {
            X  += __shfl_xor_sync(0xFFFFFFFFu, X,  m);
            Y  += __shfl_xor_sync(0xFFFFFFFFu, Y,  m);
            XY += __shfl_xor_sync(0xFFFFFFFFu, XY, m);
        }
        if (lane == 0) {
            // full-quadrant sums: 2*upper + 64 diag elems * 5.0 per split
            float Sx  = (2.f * X + 320.f * (float)PD) * (1.f / 4096.f);
            float Sy  = (2.f * Y + 320.f * (float)PD) * (1.f / 4096.f);
            float Sxy = XY * (1.f / 4096.f);
            float mx = 0.f;
#pragma unroll
            for (int k = 0; k < MSUB; k++) mx = fmaxf(mx, g_l2m[k]);
            out[0] = (Sx + Sy - 2.f * Sxy) * (1.f / 64.f);  // total_loss
            out[1] = mx;                                    // max(l2[-1])
            out[2] = Sx * (1.f / 64.f);                     // sum(xx)/P
            out[3] = Sy * (1.f / 64.f);                     // sum(yy)/P
            out[4] = Sxy * (1.f / 64.f);                    // sum(xy)/P
            out[5] = Sxy * (1.f / 64.f);                    // sum(yx)/P (= xy)
        }
    }
}

extern "C" void kernel_launch(void* const* d_in, const int* in_sizes, int n_in,
                              void* d_out, int out_size) {
    const float* src = (const float*)d_in[0];
    const float* tgt = (const float*)d_in[1];

    dim3 g1(NCH, PD);
    gram_kernel<<<g1, 256>>>(src, tgt);
    dim3 g2(MSUB, PD);
    mmd_kernel<<<g2, 256>>>((float*)d_out);
}

// round 17
// speedup vs baseline: 1.0907x; 1.0907x over previous
#include <cuda_runtime.h>
#include <cuda_bf16.h>
#include <stdint.h>

// Problem constants
#define PD 64      // splits
#define KD 64      // samples per side
#define ND 128     // points per split
#define DD 2048    // feature dim
#define NCH 4      // D quarters -> 256 CTAs, 2 per SM
#define KC (DD / NCH)     // 512 K per CTA
#define NCHK (KC / 64)    // 8 chunks of 64 K
#define STAGES 3   // smem ring depth
#define MSUB 12    // mmd CTAs per split: 4 XX + 4 YY + 4 XY

// Scratch (device globals; zero-initialized; counters self-reset)
__device__ float g_part[NCH][PD][ND][ND];  // partial grams (YX quadrant unwritten)
__device__ float g_diag[NCH][PD][ND];      // partial gram diagonals
__device__ float g_bw[NCH][PD][2];         // per-quarter (strict-upper sum, trace)
__device__ float g_sums2[PD][MSUB];        // per-CTA kernel sums
__device__ float g_l2m[MSUB];              // per-CTA max l2, split PD-1
__device__ unsigned int g_ctr;             // finalize counter (self-reset)

__device__ __forceinline__ uint32_t smem_u32(const void* p) {
    uint32_t a;
    asm("{ .reg .u64 t; cvta.to.shared.u64 t, %1; cvt.u32.u64 %0, t; }"
        : "=r"(a) : "l"(p));
    return a;
}

__device__ __forceinline__ void ldsm_x4(uint32_t& r0, uint32_t& r1, uint32_t& r2,
                                        uint32_t& r3, uint32_t addr) {
    asm volatile("ldmatrix.sync.aligned.m8n8.x4.shared.b16 {%0,%1,%2,%3}, [%4];"
                 : "=r"(r0), "=r"(r1), "=r"(r2), "=r"(r3) : "r"(addr));
}

__device__ __forceinline__ void mma_bf16(float* c, const uint32_t* a, const uint32_t* b) {
    asm volatile(
        "mma.sync.aligned.m16n8k16.row.col.f32.bf16.bf16.f32 "
        "{%0,%1,%2,%3}, {%4,%5,%6,%7}, {%8,%9}, {%0,%1,%2,%3};"
        : "+f"(c[0]), "+f"(c[1]), "+f"(c[2]), "+f"(c[3])
        : "r"(a[0]), "r"(a[1]), "r"(a[2]), "r"(a[3]), "r"(b[0]), "r"(b[1]));
}

#define BAR_SYNC(id)   asm volatile("bar.sync %0, 256;"   :: "r"(id) : "memory")
#define BAR_ARRIVE(id) asm volatile("bar.arrive %0, 256;" :: "r"(id) : "memory")

// ---------------------------------------------------------------------------
// Kernel 1: warp-specialized partial Gram.
// Warps 0-5 = consumers (one retained 32x64 tile each; YX tiles dropped by
// symmetry). Warps 6-7 = producers streaming fp32->bf16 into a 3-stage ring.
// full[s] barrier id = 1+s (producers arrive, consumers sync);
// free[s] barrier id = 4+s (consumers arrive, producers sync). Count 256.
// ---------------------------------------------------------------------------
__global__ void __launch_bounds__(256, 2) gram_kernel(const float* __restrict__ src,
                                                      const float* __restrict__ tgt) {
    const int nc = blockIdx.x;
    const int p  = blockIdx.y;
    const int t  = threadIdx.x;
    const int lane = t & 31;
    const int w    = t >> 5;

    __shared__ __align__(16) __nv_bfloat16 tile[STAGES][ND][72];  // 54 KB ring
    __shared__ float red1[8], red2[8];

    float s1 = 0.f, s2 = 0.f;   // strict-upper sum, trace contributions

    if (w >= 6) {
        // ===================== PRODUCER (warps 6,7) =====================
        const int pt  = t - 192;        // 0..63
        const int f4c = pt & 15;        // float4 column 0..15
        const int rg  = pt >> 4;        // row group 0..3
        const float* srcp = src + (size_t)(p * KD + rg) * DD + nc * KC + f4c * 4;
        const float* tgtp = tgt + (size_t)(p * KD + rg) * DD + nc * KC + f4c * 4;
        const float* pb[4] = { srcp, srcp + (size_t)32 * DD,
                               tgtp, tgtp + (size_t)32 * DD };
        char* sbase[STAGES];
#pragma unroll
        for (int s = 0; s < STAGES; s++) sbase[s] = (char*)&tile[s][0][0];
        const uint32_t sts0 = (uint32_t)(rg * 144 + f4c * 8);

        for (int ch = 0; ch < NCHK; ch++) {
            const int s = ch % STAGES;
            if (ch >= STAGES) BAR_SYNC(4 + s);   // wait stage free
            char* dst = sbase[s];
            const int co = ch * 64;

            float4 va[8], vb[8];
#pragma unroll
            for (int j = 0; j < 8; j++) va[j] = *(const float4*)(pb[0] + (size_t)j * 4 * DD + co);
#pragma unroll
            for (int j = 0; j < 8; j++) vb[j] = *(const float4*)(pb[1] + (size_t)j * 4 * DD + co);

#pragma unroll
            for (int j = 0; j < 8; j++) {   // STS batch 0
                __nv_bfloat162 lo = __floats2bfloat162_rn(va[j].x, va[j].y);
                __nv_bfloat162 hi = __floats2bfloat162_rn(va[j].z, va[j].w);
                uint2 u = { *(uint32_t*)&lo, *(uint32_t*)&hi };
                *(uint2*)(dst + sts0 + (0 * 32 + 4 * j) * 144) = u;
            }
#pragma unroll
            for (int j = 0; j < 8; j++) va[j] = *(const float4*)(pb[2] + (size_t)j * 4 * DD + co);
#pragma unroll
            for (int j = 0; j < 8; j++) {   // STS batch 1
                __nv_bfloat162 lo = __floats2bfloat162_rn(vb[j].x, vb[j].y);
                __nv_bfloat162 hi = __floats2bfloat162_rn(vb[j].z, vb[j].w);
                uint2 u = { *(uint32_t*)&lo, *(uint32_t*)&hi };
                *(uint2*)(dst + sts0 + (1 * 32 + 4 * j) * 144) = u;
            }
#pragma unroll
            for (int j = 0; j < 8; j++) vb[j] = *(const float4*)(pb[3] + (size_t)j * 4 * DD + co);
#pragma unroll
            for (int j = 0; j < 8; j++) {   // STS batch 2
                __nv_bfloat162 lo = __floats2bfloat162_rn(va[j].x, va[j].y);
                __nv_bfloat162 hi = __floats2bfloat162_rn(va[j].z, va[j].w);
                uint2 u = { *(uint32_t*)&lo, *(uint32_t*)&hi };
                *(uint2*)(dst + sts0 + (2 * 32 + 4 * j) * 144) = u;
            }
#pragma unroll
            for (int j = 0; j < 8; j++) {   // STS batch 3
                __nv_bfloat162 lo = __floats2bfloat162_rn(vb[j].x, vb[j].y);
                __nv_bfloat162 hi = __floats2bfloat162_rn(vb[j].z, vb[j].w);
                uint2 u = { *(uint32_t*)&lo, *(uint32_t*)&hi };
                *(uint2*)(dst + sts0 + (3 * 32 + 4 * j) * 144) = u;
            }
            __threadfence_block();   // make STS visible before arrival
            BAR_ARRIVE(1 + s);       // stage full
        }
        // producers contribute 0 to reductions
    } else {
        // ===================== CONSUMER (warps 0-5) =====================
        // tile map: w0 (0,0)  w1 (32,0)  w2 (0,64)  w3 (32,64)  w4 (64,64)  w5 (96,64)
        const int wm = (w < 2) ? (w << 5) : ((w - 2) << 5);
        const int wn = (w < 2) ? 0 : 64;

        const uint32_t tb0 = smem_u32(&tile[0][0][0]);
        uint32_t aoff[2], boff[4];
#pragma unroll
        for (int mi = 0; mi < 2; mi++)
            aoff[mi] = (uint32_t)((wm + mi * 16 + (lane & 15)) * 144 + (lane >> 4) * 16);
#pragma unroll
        for (int nj = 0; nj < 4; nj++)
            boff[nj] = (uint32_t)((wn + nj * 16 + ((lane >> 4) << 3) + (lane & 7)) * 144
                                  + ((lane >> 3) & 1) * 16);

        float acc[2][8][4];
#pragma unroll
        for (int mi = 0; mi < 2; mi++)
#pragma unroll
            for (int nj = 0; nj < 8; nj++)
#pragma unroll
                for (int r = 0; r < 4; r++) acc[mi][nj][r] = 0.f;

        uint32_t afr[2][2][4], bfr[2][8][2];

        for (int ch = 0; ch < NCHK; ch++) {
            const int s = ch % STAGES;
            BAR_SYNC(1 + s);   // wait stage full
            const uint32_t tbs = tb0 + (uint32_t)(s * (ND * 72 * 2));

            ldsm_x4(afr[0][0][0], afr[0][0][1], afr[0][0][2], afr[0][0][3], tbs + aoff[0]);
            ldsm_x4(afr[0][1][0], afr[0][1][1], afr[0][1][2], afr[0][1][3], tbs + aoff[1]);
#pragma unroll
            for (int nj = 0; nj < 4; nj++)
                ldsm_x4(bfr[0][2 * nj][0], bfr[0][2 * nj][1],
                        bfr[0][2 * nj + 1][0], bfr[0][2 * nj + 1][1], tbs + boff[nj]);

#pragma unroll
            for (int k16 = 0; k16 < 4; k16++) {
                const int cur = k16 & 1;
                const int nxt = cur ^ 1;
                if (k16 < 3) {
                    ldsm_x4(afr[nxt][0][0], afr[nxt][0][1], afr[nxt][0][2],
                            afr[nxt][0][3], tbs + aoff[0] + (k16 + 1) * 32);
                    ldsm_x4(afr[nxt][1][0], afr[nxt][1][1], afr[nxt][1][2],
                            afr[nxt][1][3], tbs + aoff[1] + (k16 + 1) * 32);
#pragma unroll
                    for (int nj = 0; nj < 4; nj++)
                        ldsm_x4(bfr[nxt][2 * nj][0], bfr[nxt][2 * nj][1],
                                bfr[nxt][2 * nj + 1][0], bfr[nxt][2 * nj + 1][1],
                                tbs + boff[nj] + (k16 + 1) * 32);
                }
#pragma unroll
                for (int mi = 0; mi < 2; mi++)
#pragma unroll
                    for (int nj = 0; nj < 8; nj++)
                        mma_bf16(acc[mi][nj], afr[cur][mi], bfr[cur][nj]);
            }
            BAR_ARRIVE(4 + s);   // stage free
        }

        // ---- writeout + (strict-upper sum, trace) + diag ----
        float* outp = &g_part[nc][p][0][0];
        float* diagp = &g_diag[nc][p][0];
        const int rr = lane >> 2;
        const int cc = (lane & 3) * 2;
#pragma unroll
        for (int mi = 0; mi < 2; mi++)
#pragma unroll
            for (int nj = 0; nj < 8; nj++) {
                int row = wm + mi * 16 + rr;
                int col = wn + nj * 8 + cc;
                *(float2*)&outp[row * ND + col] =
                    make_float2(acc[mi][nj][0], acc[mi][nj][1]);
                *(float2*)&outp[(row + 8) * ND + col] =
                    make_float2(acc[mi][nj][2], acc[mi][nj][3]);
                if (col > row)         s1 += acc[mi][nj][0];
                if (col + 1 > row)     s1 += acc[mi][nj][1];
                if (col > row + 8)     s1 += acc[mi][nj][2];
                if (col + 1 > row + 8) s1 += acc[mi][nj][3];
                if (row == col)         { s2 += acc[mi][nj][0]; diagp[row]     = acc[mi][nj][0]; }
                if (row == col + 1)     { s2 += acc[mi][nj][1]; diagp[row]     = acc[mi][nj][1]; }
                if (row + 8 == col)     { s2 += acc[mi][nj][2]; diagp[row + 8] = acc[mi][nj][2]; }
                if (row + 8 == col + 1) { s2 += acc[mi][nj][3]; diagp[row + 8] = acc[mi][nj][3]; }
            }
    }

#pragma unroll
    for (int m = 16; m > 0; m >>= 1) {
        s1 += __shfl_xor_sync(0xFFFFFFFFu, s1, m);
        s2 += __shfl_xor_sync(0xFFFFFFFFu, s2, m);
    }
    if (lane == 0) { red1[w] = s1; red2[w] = s2; }
    __syncthreads();
    if (t == 0) {
        float a = 0.f, b2 = 0.f;
#pragma unroll
        for (int k = 0; k < 8; k++) { a += red1[k]; b2 += red2[k]; }
        g_bw[nc][p][0] = a;    // strict-upper sum of partial gram
        g_bw[nc][p][1] = b2;   // trace of partial gram
    }
}

// ---------------------------------------------------------------------------
// Kernel 2 (unchanged R16): 768 CTAs x 256 thr, symmetric MMD.
// ---------------------------------------------------------------------------
__global__ void __launch_bounds__(256) mmd_kernel(float* __restrict__ out) {
    const int sub = blockIdx.x;
    const int p   = blockIdx.y;
    const int region = sub >> 2;      // 0=XX, 1=YY, 2=XY
    const int jb = (sub & 3) * 16;
    const int t = threadIdx.x;
    const int lane = t & 31;
    const int w = t >> 5;

    const int rr = t >> 2;
    const int cg = (t & 3) * 4;
    const int row = (region == 1) ? 64 + rr : rr;
    const int col0 = ((region == 0) ? 0 : 64) + jb + cg;

    __shared__ float praw[4][ND];
    __shared__ float diag[ND];
    __shared__ float sred[8], sred2[8];
    __shared__ unsigned int s_last;

    if (t < 128) {
        int c = t >> 5, i4 = (t & 31) * 4;
        float4 dv = *(const float4*)&g_diag[c][p][i4];
        *(float4*)&praw[c][i4] = dv;
    }
    __syncthreads();
    if (t < 128)
        diag[t] = (praw[0][t] + praw[1][t]) + (praw[2][t] + praw[3][t]);

    float gu = 0.f, tr = 0.f;
#pragma unroll
    for (int c = 0; c < NCH; c++) { gu += g_bw[c][p][0]; tr += g_bw[c][p][1]; }
    const float sumG = 2.f * gu + tr;
    const float sumL2 = 2.f * (float)ND * tr - 2.f * sumG;
    const float bwv = sumL2 / (float)(ND * ND - ND) * 0.25f;
    const float inv4 = 1.f / (bwv * 16.f + 1e-9f);
    __syncthreads();

    const int jloc0 = jb + cg;
    const bool active = (region == 2) || (rr < jloc0 + 3);

    float qs = 0.f, lmax = 0.f;
    if (active) {
        float4 A = *(const float4*)&g_part[0][p][row][col0];
        float4 B = *(const float4*)&g_part[1][p][row][col0];
        float4 C = *(const float4*)&g_part[2][p][row][col0];
        float4 D = *(const float4*)&g_part[3][p][row][col0];
        float g[4] = { (A.x + B.x) + (C.x + D.x),
                       (A.y + B.y) + (C.y + D.y),
                       (A.z + B.z) + (C.z + D.z),
                       (A.w + B.w) + (C.w + D.w) };
        const float di = diag[row];
#pragma unroll
        for (int jj = 0; jj < 4; jj++) {
            bool use = (region == 2) || (jloc0 + jj > rr);
            if (use) {
                float l2 = di + diag[col0 + jj] - 2.f * g[jj];
                lmax = fmaxf(lmax, l2);
                float z = __expf(-l2 * inv4);
                float z2 = z * z;
                float z4 = z2 * z2;
                float z8 = z4 * z4;
                float z16 = z8 * z8;
                qs += z + z2 + z4 + z8 + z16;
            }
        }
    }

#pragma unroll
    for (int m = 16; m > 0; m >>= 1) {
        qs += __shfl_xor_sync(0xFFFFFFFFu, qs, m);
        lmax = fmaxf(lmax, __shfl_xor_sync(0xFFFFFFFFu, lmax, m));
    }
    if (lane == 0) { sred[w] = qs; sred2[w] = lmax; }
    __syncthreads();

    if (t == 0) {
        float s = 0.f, m = 0.f;
#pragma unroll
        for (int k = 0; k < 8; k++) { s += sred[k]; m = fmaxf(m, sred2[k]); }
        g_sums2[p][sub] = s;
        if (p == PD - 1) g_l2m[sub] = m;
        __threadfence();
        unsigned int done = atomicAdd(&g_ctr, 1u);
        s_last = (done == (unsigned)(MSUB * PD - 1)) ? 1u : 0u;
        if (s_last) g_ctr = 0;
    }
    __syncthreads();

    if (s_last != 0 && w == 0) {
        __threadfence();
        float X = 0.f, Y = 0.f, XY = 0.f;
#pragma unroll
        for (int pp = lane; pp < PD; pp += 32) {
            const float* s = &g_sums2[pp][0];
            float4 a0 = *(const float4*)&s[0];
            float4 a1 = *(const float4*)&s[4];
            float4 a2 = *(const float4*)&s[8];
            X  += (a0.x + a0.y) + (a0.z + a0.w);
            Y  += (a1.x + a1.y) + (a1.z + a1.w);
            XY += (a2.x + a2.y) + (a2.z + a2.w);
        }
#pragma unroll
        for (int m = 16; m > 0; m >>= 1) {
            X  += __shfl_xor_sync(0xFFFFFFFFu, X,  m);
            Y  += __shfl_xor_sync(0xFFFFFFFFu, Y,  m);
            XY += __shfl_xor_sync(0xFFFFFFFFu, XY, m);
        }
        if (lane == 0) {
            float Sx  = (2.f * X + 320.f * (float)PD) * (1.f / 4096.f);
            float Sy  = (2.f * Y + 320.f * (float)PD) * (1.f / 4096.f);
            float Sxy = XY * (1.f / 4096.f);
            float mx = 0.f;
#pragma unroll
            for (int k = 0; k < MSUB; k++) mx = fmaxf(mx, g_l2m[k]);
            out[0] = (Sx + Sy - 2.f * Sxy) * (1.f / 64.f);
            out[1] = mx;
            out[2] = Sx * (1.f / 64.f);
            out[3] = Sy * (1.f / 64.f);
            out[4] = Sxy * (1.f / 64.f);
            out[5] = Sxy * (1.f / 64.f);
        }
    }
}

extern "C" void kernel_launch(void* const* d_in, const int* in_sizes, int n_in,
                              void* d_out, int out_size) {
    const float* src = (const float*)d_in[0];
    const float* tgt = (const float*)d_in[1];

    dim3 g1(NCH, PD);
    gram_kernel<<<g1, 256>>>(src, tgt);
    dim3 g2(MSUB, PD);
    mmd_kernel<<<g2, 256>>>((float*)d_out);
}